// round 8
// baseline (speedup 1.0000x reference)
#include <cuda_runtime.h>
#include <cuda_bf16.h>
#include <math.h>
#include <stdint.h>

#define BB 16
#define NN 200
#define DD 2048
#define HH 2048
#define MM (BB * NN)          // 3200
#define AELEMS (MM * DD)      // 6,553,600
#define WELEMS (DD * HH)      // 4,194,304

// ---------------- scratch (no allocations allowed) ----------------
__device__ float g_lq[MM * HH];
__device__ float g_lk[MM * HH];
__device__ float g_lv[MM * HH];
__device__ float g_lloc[MM * HH];
__device__ float g_kloc[MM * HH];
__device__ float g_scores[BB * NN * NN];

__device__ __nv_bfloat16 g_ahi[4][AELEMS];   // q, k, v, loc
__device__ __nv_bfloat16 g_alo[4][AELEMS];
__device__ __nv_bfloat16 g_whi[5][WELEMS];   // W row-major [k][n]
__device__ __nv_bfloat16 g_wlo[5][WELEMS];

// ---------------- PTX helpers ----------------
__device__ __forceinline__ void cpa16(void* smem, const void* gmem) {
    unsigned a = (unsigned)__cvta_generic_to_shared(smem);
    asm volatile("cp.async.cg.shared.global [%0], [%1], 16;\n" :: "r"(a), "l"(gmem));
}
__device__ __forceinline__ void cpa_commit() { asm volatile("cp.async.commit_group;\n"); }
template <int N> __device__ __forceinline__ void cpa_wait() {
    asm volatile("cp.async.wait_group %0;\n" :: "n"(N));
}
__device__ __forceinline__ void ldm_x4(unsigned* r, const void* p) {
    unsigned a = (unsigned)__cvta_generic_to_shared(p);
    asm volatile("ldmatrix.sync.aligned.m8n8.x4.shared.b16 {%0,%1,%2,%3}, [%4];\n"
                 : "=r"(r[0]), "=r"(r[1]), "=r"(r[2]), "=r"(r[3]) : "r"(a));
}
__device__ __forceinline__ void ldm_x4t(unsigned* r, const void* p) {
    unsigned a = (unsigned)__cvta_generic_to_shared(p);
    asm volatile("ldmatrix.sync.aligned.m8n8.x4.trans.shared.b16 {%0,%1,%2,%3}, [%4];\n"
                 : "=r"(r[0]), "=r"(r[1]), "=r"(r[2]), "=r"(r[3]) : "r"(a));
}
__device__ __forceinline__ void mma_bf16(float* d, const unsigned* a, const unsigned* b) {
    asm volatile("mma.sync.aligned.m16n8k16.row.col.f32.bf16.bf16.f32 "
                 "{%0,%1,%2,%3},{%4,%5,%6,%7},{%8,%9},{%0,%1,%2,%3};\n"
                 : "+f"(d[0]), "+f"(d[1]), "+f"(d[2]), "+f"(d[3])
                 : "r"(a[0]), "r"(a[1]), "r"(a[2]), "r"(a[3]), "r"(b[0]), "r"(b[1]));
}

// ---------------- fp32 -> bf16 hi/lo split ----------------
struct CvtSrc { const float* p[9]; };

__global__ __launch_bounds__(256) void cvt_split(CvtSrc s) {
    const int z = blockIdx.y;
    const int cnt = (z < 4) ? AELEMS : WELEMS;
    const int i = (blockIdx.x * 256 + threadIdx.x) * 4;
    if (i >= cnt) return;
    __nv_bfloat16* hi;
    __nv_bfloat16* lo;
    if (z < 4) { hi = g_ahi[z];     lo = g_alo[z]; }
    else       { hi = g_whi[z - 4]; lo = g_wlo[z - 4]; }
    float4 v = *(const float4*)(s.p[z] + i);
    float vv[4] = { v.x, v.y, v.z, v.w };
    __nv_bfloat16 h[4], l[4];
    #pragma unroll
    for (int j = 0; j < 4; j++) {
        h[j] = __float2bfloat16(vv[j]);
        l[j] = __float2bfloat16(vv[j] - __bfloat162float(h[j]));
    }
    __nv_bfloat162 t;
    t.x = h[0]; t.y = h[1]; *(__nv_bfloat162*)(hi + i)     = t;
    t.x = h[2]; t.y = h[3]; *(__nv_bfloat162*)(hi + i + 2) = t;
    t.x = l[0]; t.y = l[1]; *(__nv_bfloat162*)(lo + i)     = t;
    t.x = l[2]; t.y = l[3]; *(__nv_bfloat162*)(lo + i + 2) = t;
}

// ---------------- projection GEMM (split-bf16, 3 MMAs, 3-stage pipeline) ------
// C_z = A_z @ W_z + b_z ; M=3200, N=2048, K=2048. Block 128x128, BK=32,
// 8 warps (4m x 2n), warp tile 32x64, cp.async 3-stage, frag prefetch.
#define BK 32
#define NITER (DD / BK)            // 64
#define A_ST_BYTES 20480           // 2 prec * 128 * 40 * 2
#define B_ST_BYTES 17408           // 2 prec * 32 * 136 * 2
#define STG_BYTES (A_ST_BYTES + B_ST_BYTES)   // 37888
#define SMEM_PROJ (3 * STG_BYTES)             // 113664

__device__ __forceinline__ void load_stage(
    char* stage,
    const __nv_bfloat16* __restrict__ Ahi, const __nv_bfloat16* __restrict__ Alo,
    const __nv_bfloat16* __restrict__ Whi, const __nv_bfloat16* __restrict__ Wlo,
    int brow, int bcol, int kbase, int tid)
{
    // A: 2 prec x 128 rows x 32 k  (pitch 40 bf16 = 80B)
    #pragma unroll
    for (int it = tid; it < 1024; it += 256) {
        int prec = it >> 9, rem = it & 511;
        int row = rem >> 2, kc = (rem & 3) * 8;
        const __nv_bfloat16* src =
            (prec ? Alo : Ahi) + (size_t)(brow + row) * DD + kbase + kc;
        cpa16(stage + prec * 10240 + row * 80 + kc * 2, src);
    }
    // B: 2 prec x 32 k x 128 n  (pitch 136 bf16 = 272B)
    #pragma unroll
    for (int it = tid; it < 1024; it += 256) {
        int prec = it >> 9, rem = it & 511;
        int krow = rem >> 4, col = (rem & 15) * 8;
        const __nv_bfloat16* src =
            (prec ? Wlo : Whi) + (size_t)(kbase + krow) * HH + bcol + col;
        cpa16(stage + A_ST_BYTES + prec * 8704 + krow * 272 + col * 2, src);
    }
}

__device__ __forceinline__ void ld_frags(
    const char* stage, int kk, int wm, int wn, int lrow, int lco,
    unsigned af[2][2][4], unsigned bfr[2][8][2])
{
    const char* sAb = stage;
    const char* sBb = stage + A_ST_BYTES;
    #pragma unroll
    for (int p = 0; p < 2; p++)
        #pragma unroll
        for (int mi = 0; mi < 2; mi++)
            ldm_x4(af[p][mi],
                   sAb + p * 10240 + (wm * 32 + mi * 16 + lrow) * 80 + (kk * 16 + lco) * 2);
    #pragma unroll
    for (int p = 0; p < 2; p++)
        #pragma unroll
        for (int g = 0; g < 4; g++) {
            unsigned r[4];
            ldm_x4t(r, sBb + p * 8704 + (kk * 16 + lrow) * 272 +
                        (wn * 64 + g * 16 + lco) * 2);
            bfr[p][2 * g][0]     = r[0];
            bfr[p][2 * g][1]     = r[1];
            bfr[p][2 * g + 1][0] = r[2];
            bfr[p][2 * g + 1][1] = r[3];
        }
}

__device__ __forceinline__ void do_mma(
    float acc[2][8][4], unsigned af[2][2][4], unsigned bfr[2][8][2])
{
    #pragma unroll
    for (int mi = 0; mi < 2; mi++)
        #pragma unroll
        for (int ni = 0; ni < 8; ni++) {
            mma_bf16(acc[mi][ni], af[0][mi], bfr[0][ni]);  // hi*hi
            mma_bf16(acc[mi][ni], af[0][mi], bfr[1][ni]);  // hi*lo
            mma_bf16(acc[mi][ni], af[1][mi], bfr[0][ni]);  // lo*hi
        }
}

__global__ __launch_bounds__(256, 1) void proj_mma(const float* __restrict__ bq,
                                                   const float* __restrict__ bk,
                                                   const float* __restrict__ bv,
                                                   const float* __restrict__ bloc,
                                                   const float* __restrict__ blk) {
    extern __shared__ char smem[];
    const int z  = blockIdx.z;
    const int ai = (z == 4) ? 3 : z;
    const __nv_bfloat16* __restrict__ Ahi = g_ahi[ai];
    const __nv_bfloat16* __restrict__ Alo = g_alo[ai];
    const __nv_bfloat16* __restrict__ Whi = g_whi[z];
    const __nv_bfloat16* __restrict__ Wlo = g_wlo[z];
    const float* bias;
    float* C;
    switch (z) {
        case 0: bias = bq;   C = g_lq;   break;
        case 1: bias = bk;   C = g_lk;   break;
        case 2: bias = bv;   C = g_lv;   break;
        case 3: bias = bloc; C = g_lloc; break;
        default: bias = blk; C = g_kloc; break;
    }

    const int tid  = threadIdx.x;
    const int lane = tid & 31;
    const int wid  = tid >> 5;
    const int wm   = wid & 3;
    const int wn   = wid >> 2;
    const int brow = blockIdx.y * 128;
    const int bcol = blockIdx.x * 128;
    const int lrow = lane & 15;
    const int lco  = (lane >> 4) * 8;

    float acc[2][8][4];
    #pragma unroll
    for (int mi = 0; mi < 2; mi++)
        #pragma unroll
        for (int ni = 0; ni < 8; ni++)
            #pragma unroll
            for (int j = 0; j < 4; j++) acc[mi][ni][j] = 0.f;

    char* stg[3] = { smem, smem + STG_BYTES, smem + 2 * STG_BYTES };

    // prologue: stages 0, 1
    load_stage(stg[0], Ahi, Alo, Whi, Wlo, brow, bcol, 0, tid);
    cpa_commit();
    load_stage(stg[1], Ahi, Alo, Whi, Wlo, brow, bcol, BK, tid);
    cpa_commit();

    for (int i = 0; i < NITER; i++) {
        char* st = stg[i % 3];
        // issue load of stage i+2 (overwrites stage computed at i-1; safe: the
        // end-of-iter barrier of i-1 has been passed by all warps)
        if (i + 2 < NITER) {
            load_stage(stg[(i + 2) % 3], Ahi, Alo, Whi, Wlo, brow, bcol,
                       (i + 2) * BK, tid);
            cpa_commit();
            cpa_wait<2>();
        } else if (i + 1 < NITER) {
            cpa_wait<1>();
        } else {
            cpa_wait<0>();
        }
        __syncthreads();

        unsigned af0[2][2][4], bf0[2][8][2];
        unsigned af1[2][2][4], bf1[2][8][2];
        ld_frags(st, 0, wm, wn, lrow, lco, af0, bf0);
        ld_frags(st, 1, wm, wn, lrow, lco, af1, bf1);
        do_mma(acc, af0, bf0);
        do_mma(acc, af1, bf1);
        __syncthreads();
    }

    // epilogue: bias + store fp32
    const int lr = lane >> 2;
    const int lc = (lane & 3) * 2;
    #pragma unroll
    for (int mi = 0; mi < 2; mi++) {
        #pragma unroll
        for (int ni = 0; ni < 8; ni++) {
            const int col = bcol + wn * 64 + ni * 8 + lc;
            const float b0 = bias[col], b1 = bias[col + 1];
            int row = brow + wm * 32 + mi * 16 + lr;
            *(float2*)&C[(size_t)row * HH + col] =
                make_float2(acc[mi][ni][0] + b0, acc[mi][ni][1] + b1);
            row += 8;
            *(float2*)&C[(size_t)row * HH + col] =
                make_float2(acc[mi][ni][2] + b0, acc[mi][ni][3] + b1);
        }
    }
}

// ---------------- scores = (lq+p)@lk^T + (lq+lloc)@kloc^T, scaled ----------------
__global__ __launch_bounds__(256) void scores_kernel(const float* __restrict__ param) {
    const int b    = blockIdx.z;
    const int brow = blockIdx.y * 64;
    const int bcol = blockIdx.x * 64;

    __shared__ float As[8][64];
    __shared__ float Bs[8][64];

    const int tid = threadIdx.x;
    const int ty = tid >> 4, tx = tid & 15;

    float acc[4][4];
    #pragma unroll
    for (int i = 0; i < 4; i++)
        #pragma unroll
        for (int j = 0; j < 4; j++) acc[i][j] = 0.f;

    for (int k0 = 0; k0 < 2 * HH; k0 += 8) {
        const bool first = (k0 < HH);
        const int  h0    = k0 & (HH - 1);
        const float* __restrict__ Aadd = first ? param : g_lloc;
        const float* __restrict__ Bmat = first ? g_lk  : g_kloc;

        #pragma unroll
        for (int l = tid; l < 512; l += 256) {
            int k = l & 7, n = l >> 3;
            int row = brow + n;
            float v = 0.f;
            if (row < NN) {
                size_t idx = (size_t)(b * NN + row) * HH + h0 + k;
                v = g_lq[idx] + Aadd[idx];
            }
            As[k][n] = v;
        }
        #pragma unroll
        for (int l = tid; l < 512; l += 256) {
            int k = l & 7, m = l >> 3;
            int row = bcol + m;
            float v = 0.f;
            if (row < NN) v = Bmat[(size_t)(b * NN + row) * HH + h0 + k];
            Bs[k][m] = v;
        }
        __syncthreads();

        #pragma unroll
        for (int k = 0; k < 8; k++) {
            float a[4], bb[4];
            #pragma unroll
            for (int i = 0; i < 4; i++) a[i] = As[k][ty * 4 + i];
            #pragma unroll
            for (int j = 0; j < 4; j++) bb[j] = Bs[k][tx * 4 + j];
            #pragma unroll
            for (int i = 0; i < 4; i++)
                #pragma unroll
                for (int j = 0; j < 4; j++)
                    acc[i][j] = fmaf(a[i], bb[j], acc[i][j]);
        }
        __syncthreads();
    }

    const float scale = 0.022097086912079612f;  // 1/sqrt(2048)
    #pragma unroll
    for (int i = 0; i < 4; i++) {
        int row = brow + ty * 4 + i;
        if (row >= NN) continue;
        #pragma unroll
        for (int j = 0; j < 4; j++) {
            int col = bcol + tx * 4 + j;
            if (col < NN)
                g_scores[(size_t)(b * NN + row) * NN + col] = acc[i][j] * scale;
        }
    }
}

// ---------------- row softmax over m=200 ----------------
__global__ __launch_bounds__(256) void softmax_kernel() {
    const int row = blockIdx.x;
    float* s = g_scores + (size_t)row * NN;
    const int tid = threadIdx.x;

    __shared__ float red[8];

    float v = (tid < NN) ? s[tid] : -1e30f;

    float m = v;
    #pragma unroll
    for (int o = 16; o > 0; o >>= 1) m = fmaxf(m, __shfl_xor_sync(0xffffffffu, m, o));
    if ((tid & 31) == 0) red[tid >> 5] = m;
    __syncthreads();
    float mx = red[0];
    #pragma unroll
    for (int i = 1; i < 8; i++) mx = fmaxf(mx, red[i]);
    __syncthreads();

    float e = (tid < NN) ? expf(v - mx) : 0.f;

    float sm = e;
    #pragma unroll
    for (int o = 16; o > 0; o >>= 1) sm += __shfl_xor_sync(0xffffffffu, sm, o);
    if ((tid & 31) == 0) red[tid >> 5] = sm;
    __syncthreads();
    float total = 0.f;
    #pragma unroll
    for (int i = 0; i < 8; i++) total += red[i];

    if (tid < NN) s[tid] = e / total;
}

// ---------------- out = attn @ lv ----------------
__global__ __launch_bounds__(256) void out_gemm(float* __restrict__ out) {
    const int b    = blockIdx.z;
    const int brow = blockIdx.y * 64;
    const int bcol = blockIdx.x * 64;

    __shared__ float As[8][64];
    __shared__ float Bs[8][64];

    const int tid = threadIdx.x;
    const int ty = tid >> 4, tx = tid & 15;

    float acc[4][4];
    #pragma unroll
    for (int i = 0; i < 4; i++)
        #pragma unroll
        for (int j = 0; j < 4; j++) acc[i][j] = 0.f;

    for (int k0 = 0; k0 < NN; k0 += 8) {
        #pragma unroll
        for (int l = tid; l < 512; l += 256) {
            int k = l & 7, n = l >> 3;
            int row = brow + n;
            float v = 0.f;
            if (row < NN)
                v = g_scores[(size_t)(b * NN + row) * NN + k0 + k];
            As[k][n] = v;
        }
        #pragma unroll
        for (int l = tid; l < 512; l += 256) {
            int k = l >> 6, m = l & 63;
            Bs[k][m] = g_lv[(size_t)(b * NN + k0 + k) * HH + bcol + m];
        }
        __syncthreads();

        #pragma unroll
        for (int k = 0; k < 8; k++) {
            float a[4], bb[4];
            #pragma unroll
            for (int i = 0; i < 4; i++) a[i] = As[k][ty * 4 + i];
            #pragma unroll
            for (int j = 0; j < 4; j++) bb[j] = Bs[k][tx * 4 + j];
            #pragma unroll
            for (int i = 0; i < 4; i++)
                #pragma unroll
                for (int j = 0; j < 4; j++)
                    acc[i][j] = fmaf(a[i], bb[j], acc[i][j]);
        }
        __syncthreads();
    }

    #pragma unroll
    for (int i = 0; i < 4; i++) {
        int row = brow + ty * 4 + i;
        if (row >= NN) continue;
        #pragma unroll
        for (int j = 0; j < 4; j++) {
            int col = bcol + tx * 4 + j;
            out[(size_t)(b * NN + row) * HH + col] = acc[i][j];
        }
    }
}

// ---------------- launch ----------------
extern "C" void kernel_launch(void* const* d_in, const int* in_sizes, int n_in,
                              void* d_out, int out_size) {
    const float* input_query = (const float*)d_in[0];
    const float* input_key   = (const float*)d_in[1];
    const float* input_value = (const float*)d_in[2];
    const float* loc_vector  = (const float*)d_in[3];
    const float* Wq   = (const float*)d_in[4];
    const float* bq   = (const float*)d_in[5];
    const float* Wk   = (const float*)d_in[6];
    const float* bk   = (const float*)d_in[7];
    const float* Wv   = (const float*)d_in[8];
    const float* bv   = (const float*)d_in[9];
    const float* Wloc = (const float*)d_in[10];
    const float* bloc = (const float*)d_in[11];
    const float* Wlk  = (const float*)d_in[12];
    const float* blk  = (const float*)d_in[13];
    const float* param = (const float*)d_in[14];
    float* out = (float*)d_out;

    static int smem_set = 0;
    if (!smem_set) {
        cudaFuncSetAttribute(proj_mma, cudaFuncAttributeMaxDynamicSharedMemorySize,
                             SMEM_PROJ);
        smem_set = 1;
    }

    // 0) split fp32 -> bf16 hi/lo (4 inputs + 5 weights)
    CvtSrc cs;
    cs.p[0] = input_query; cs.p[1] = input_key; cs.p[2] = input_value; cs.p[3] = loc_vector;
    cs.p[4] = Wq; cs.p[5] = Wk; cs.p[6] = Wv; cs.p[7] = Wloc; cs.p[8] = Wlk;
    cvt_split<<<dim3(AELEMS / 1024, 9), 256>>>(cs);

    // 1) five projections on tensor cores (3-stage pipeline)
    proj_mma<<<dim3(HH / 128, MM / 128, 5), 256, SMEM_PROJ>>>(bq, bk, bv, bloc, blk);

    // 2) scores (fused q+param / q+lloc adds), scaled
    scores_kernel<<<dim3(4, 4, BB), 256>>>(param);

    // 3) softmax over m
    softmax_kernel<<<MM, 256>>>();

    // 4) attn @ lv -> out
    out_gemm<<<dim3(HH / 64, 4, BB), 256>>>(out);
}

// round 15
// speedup vs baseline: 1.3290x; 1.3290x over previous
#include <cuda_runtime.h>
#include <cuda_fp16.h>
#include <math.h>
#include <stdint.h>

#define BB 16
#define NN 200
#define DD 2048
#define HH 2048
#define MM (BB * NN)          // 3200
#define AELEMS (MM * DD)      // 6,553,600
#define WELEMS (DD * HH)      // 4,194,304

// ---------------- scratch (no allocations allowed) ----------------
__device__ float g_lq[MM * HH];
__device__ float g_lk[MM * HH];
__device__ float g_lv[MM * HH];
__device__ float g_lloc[MM * HH];
__device__ float g_kloc[MM * HH];
__device__ float g_scores[BB * NN * NN];

__device__ __half g_ahi[4][AELEMS];   // q, k, v, loc  (fp16 hi)
__device__ __half g_alo[4][AELEMS];   // fp16 residual
__device__ __half g_wh[5][WELEMS];    // W single fp16, row-major [k][n]

// ---------------- PTX helpers ----------------
__device__ __forceinline__ void cpa16(void* smem, const void* gmem) {
    unsigned a = (unsigned)__cvta_generic_to_shared(smem);
    asm volatile("cp.async.cg.shared.global [%0], [%1], 16;\n" :: "r"(a), "l"(gmem));
}
__device__ __forceinline__ void cpa_commit() { asm volatile("cp.async.commit_group;\n"); }
template <int N> __device__ __forceinline__ void cpa_wait() {
    asm volatile("cp.async.wait_group %0;\n" :: "n"(N));
}
__device__ __forceinline__ void ldm_x4(unsigned* r, const void* p) {
    unsigned a = (unsigned)__cvta_generic_to_shared(p);
    asm volatile("ldmatrix.sync.aligned.m8n8.x4.shared.b16 {%0,%1,%2,%3}, [%4];\n"
                 : "=r"(r[0]), "=r"(r[1]), "=r"(r[2]), "=r"(r[3]) : "r"(a));
}
__device__ __forceinline__ void ldm_x4t(unsigned* r, const void* p) {
    unsigned a = (unsigned)__cvta_generic_to_shared(p);
    asm volatile("ldmatrix.sync.aligned.m8n8.x4.trans.shared.b16 {%0,%1,%2,%3}, [%4];\n"
                 : "=r"(r[0]), "=r"(r[1]), "=r"(r[2]), "=r"(r[3]) : "r"(a));
}
__device__ __forceinline__ void mma_f16(float* d, const unsigned* a, const unsigned* b) {
    asm volatile("mma.sync.aligned.m16n8k16.row.col.f32.f16.f16.f32 "
                 "{%0,%1,%2,%3},{%4,%5,%6,%7},{%8,%9},{%0,%1,%2,%3};\n"
                 : "+f"(d[0]), "+f"(d[1]), "+f"(d[2]), "+f"(d[3])
                 : "r"(a[0]), "r"(a[1]), "r"(a[2]), "r"(a[3]), "r"(b[0]), "r"(b[1]));
}

// ---------------- fp32 -> fp16 conversions ----------------
struct CvtSrc { const float* p[9]; };

__global__ __launch_bounds__(256) void cvt_split(CvtSrc s) {
    const int z = blockIdx.y;
    const int cnt = (z < 4) ? AELEMS : WELEMS;
    const int i = (blockIdx.x * 256 + threadIdx.x) * 4;
    if (i >= cnt) return;
    float4 v = *(const float4*)(s.p[z] + i);
    float vv[4] = { v.x, v.y, v.z, v.w };
    if (z < 4) {
        __half* hi = g_ahi[z];
        __half* lo = g_alo[z];
        __half h[4], l[4];
        #pragma unroll
        for (int j = 0; j < 4; j++) {
            h[j] = __float2half(vv[j]);
            l[j] = __float2half(vv[j] - __half2float(h[j]));
        }
        __half2 t;
        t.x = h[0]; t.y = h[1]; *(__half2*)(hi + i)     = t;
        t.x = h[2]; t.y = h[3]; *(__half2*)(hi + i + 2) = t;
        t.x = l[0]; t.y = l[1]; *(__half2*)(lo + i)     = t;
        t.x = l[2]; t.y = l[3]; *(__half2*)(lo + i + 2) = t;
    } else {
        __half* w = g_wh[z - 4];
        __half2 t;
        t.x = __float2half(vv[0]); t.y = __float2half(vv[1]); *(__half2*)(w + i)     = t;
        t.x = __float2half(vv[2]); t.y = __float2half(vv[3]); *(__half2*)(w + i + 2) = t;
    }
}

// ---------------- projection GEMM (fp16 A-split, 2 MMAs) ----------------------
// C_z = A_z @ W_z + b_z ; M=3200, N=2048, K=2048. Block 128x128, BK=16,
// 8 warps (4m x 2n), warp tile 32x64, cp.async double buffer. (R3 structure.)
__global__ __launch_bounds__(256) void proj_mma(const float* __restrict__ bq,
                                                const float* __restrict__ bk,
                                                const float* __restrict__ bv,
                                                const float* __restrict__ bloc,
                                                const float* __restrict__ blk) {
    const int z  = blockIdx.z;
    const int ai = (z == 4) ? 3 : z;
    const __half* __restrict__ Ahi = g_ahi[ai];
    const __half* __restrict__ Alo = g_alo[ai];
    const __half* __restrict__ W   = g_wh[z];
    const float* bias;
    float* C;
    switch (z) {
        case 0: bias = bq;   C = g_lq;   break;
        case 1: bias = bk;   C = g_lk;   break;
        case 2: bias = bv;   C = g_lv;   break;
        case 3: bias = bloc; C = g_lloc; break;
        default: bias = blk; C = g_kloc; break;
    }

    __shared__ __align__(16) __half sA[2][2][128][24];  // [stage][prec][m][k] pad->24
    __shared__ __align__(16) __half sB[2][16][136];     // [stage][k][n] pad->136

    const int tid  = threadIdx.x;
    const int lane = tid & 31;
    const int wid  = tid >> 5;
    const int wm   = wid & 3;      // 0..3  (m)
    const int wn   = wid >> 2;     // 0..1  (n)
    const int brow = blockIdx.y * 128;
    const int bcol = blockIdx.x * 128;

    const int ar  = tid >> 1;           // A row 0..127
    const int ac  = (tid & 1) * 8;      // A k offset 0/8
    const int bkk = tid >> 4;           // B k row 0..15
    const int bs  = (tid & 15) * 8;     // B col offset

    float acc[2][8][4];
    #pragma unroll
    for (int mi = 0; mi < 2; mi++)
        #pragma unroll
        for (int ni = 0; ni < 8; ni++)
            #pragma unroll
            for (int j = 0; j < 4; j++) acc[mi][ni][j] = 0.f;

    const size_t aOff  = (size_t)(brow + ar) * DD + ac;
    const size_t bOff0 = (size_t)bkk * HH + bcol + bs;

    // prologue: stage 0
    cpa16(&sA[0][0][ar][ac], Ahi + aOff);
    cpa16(&sA[0][1][ar][ac], Alo + aOff);
    cpa16(&sB[0][bkk][bs],   W + bOff0);
    cpa_commit();

    const int NK = DD / 16;  // 128
    const int lrow = lane & 15;
    const int lco  = (lane >> 4) * 8;

    for (int i = 0; i < NK; i++) {
        const int st = i & 1;
        if (i + 1 < NK) {
            const int ns = st ^ 1;
            const int k0 = (i + 1) * 16;
            cpa16(&sA[ns][0][ar][ac], Ahi + aOff + k0);
            cpa16(&sA[ns][1][ar][ac], Alo + aOff + k0);
            cpa16(&sB[ns][bkk][bs],   W + bOff0 + (size_t)k0 * HH);
            cpa_commit();
            cpa_wait<1>();
        } else {
            cpa_wait<0>();
        }
        __syncthreads();

        unsigned afrag[2][2][4];   // [prec][mtile][4]
        #pragma unroll
        for (int p = 0; p < 2; p++)
            #pragma unroll
            for (int mi = 0; mi < 2; mi++)
                ldm_x4(afrag[p][mi], &sA[st][p][wm * 32 + mi * 16 + lrow][lco]);

        unsigned bfrag[8][2];      // [ntile][2]
        #pragma unroll
        for (int g = 0; g < 4; g++) {
            unsigned r[4];
            ldm_x4t(r, &sB[st][lrow][wn * 64 + g * 16 + lco]);
            bfrag[2 * g][0]     = r[0];
            bfrag[2 * g][1]     = r[1];
            bfrag[2 * g + 1][0] = r[2];
            bfrag[2 * g + 1][1] = r[3];
        }

        #pragma unroll
        for (int mi = 0; mi < 2; mi++)
            #pragma unroll
            for (int ni = 0; ni < 8; ni++) {
                mma_f16(acc[mi][ni], afrag[0][mi], bfrag[ni]);  // hi * W
                mma_f16(acc[mi][ni], afrag[1][mi], bfrag[ni]);  // lo * W
            }
        __syncthreads();
    }

    // epilogue: bias + store fp32
    const int lr = lane >> 2;
    const int lc = (lane & 3) * 2;
    #pragma unroll
    for (int mi = 0; mi < 2; mi++) {
        #pragma unroll
        for (int ni = 0; ni < 8; ni++) {
            const int col = bcol + wn * 64 + ni * 8 + lc;
            const float b0 = bias[col], b1 = bias[col + 1];
            int row = brow + wm * 32 + mi * 16 + lr;
            *(float2*)&C[(size_t)row * HH + col] =
                make_float2(acc[mi][ni][0] + b0, acc[mi][ni][1] + b1);
            row += 8;
            *(float2*)&C[(size_t)row * HH + col] =
                make_float2(acc[mi][ni][2] + b0, acc[mi][ni][3] + b1);
        }
    }
}

// ---------------- scores = (lq+p)@lk^T + (lq+lloc)@kloc^T, scaled ----------------
__global__ __launch_bounds__(256) void scores_kernel(const float* __restrict__ param) {
    const int b    = blockIdx.z;
    const int brow = blockIdx.y * 64;
    const int bcol = blockIdx.x * 64;

    __shared__ float As[8][64];
    __shared__ float Bs[8][64];

    const int tid = threadIdx.x;
    const int ty = tid >> 4, tx = tid & 15;

    float acc[4][4];
    #pragma unroll
    for (int i = 0; i < 4; i++)
        #pragma unroll
        for (int j = 0; j < 4; j++) acc[i][j] = 0.f;

    for (int k0 = 0; k0 < 2 * HH; k0 += 8) {
        const bool first = (k0 < HH);
        const int  h0    = k0 & (HH - 1);
        const float* __restrict__ Aadd = first ? param : g_lloc;
        const float* __restrict__ Bmat = first ? g_lk  : g_kloc;

        #pragma unroll
        for (int l = tid; l < 512; l += 256) {
            int k = l & 7, n = l >> 3;
            int row = brow + n;
            float v = 0.f;
            if (row < NN) {
                size_t idx = (size_t)(b * NN + row) * HH + h0 + k;
                v = g_lq[idx] + Aadd[idx];
            }
            As[k][n] = v;
        }
        #pragma unroll
        for (int l = tid; l < 512; l += 256) {
            int k = l & 7, m = l >> 3;
            int row = bcol + m;
            float v = 0.f;
            if (row < NN) v = Bmat[(size_t)(b * NN + row) * HH + h0 + k];
            Bs[k][m] = v;
        }
        __syncthreads();

        #pragma unroll
        for (int k = 0; k < 8; k++) {
            float a[4], bb[4];
            #pragma unroll
            for (int i = 0; i < 4; i++) a[i] = As[k][ty * 4 + i];
            #pragma unroll
            for (int j = 0; j < 4; j++) bb[j] = Bs[k][tx * 4 + j];
            #pragma unroll
            for (int i = 0; i < 4; i++)
                #pragma unroll
                for (int j = 0; j < 4; j++)
                    acc[i][j] = fmaf(a[i], bb[j], acc[i][j]);
        }
        __syncthreads();
    }

    const float scale = 0.022097086912079612f;  // 1/sqrt(2048)
    #pragma unroll
    for (int i = 0; i < 4; i++) {
        int row = brow + ty * 4 + i;
        if (row >= NN) continue;
        #pragma unroll
        for (int j = 0; j < 4; j++) {
            int col = bcol + tx * 4 + j;
            if (col < NN)
                g_scores[(size_t)(b * NN + row) * NN + col] = acc[i][j] * scale;
        }
    }
}

// ---------------- row softmax over m=200 ----------------
__global__ __launch_bounds__(256) void softmax_kernel() {
    const int row = blockIdx.x;
    float* s = g_scores + (size_t)row * NN;
    const int tid = threadIdx.x;

    __shared__ float red[8];

    float v = (tid < NN) ? s[tid] : -1e30f;

    float m = v;
    #pragma unroll
    for (int o = 16; o > 0; o >>= 1) m = fmaxf(m, __shfl_xor_sync(0xffffffffu, m, o));
    if ((tid & 31) == 0) red[tid >> 5] = m;
    __syncthreads();
    float mx = red[0];
    #pragma unroll
    for (int i = 1; i < 8; i++) mx = fmaxf(mx, red[i]);
    __syncthreads();

    float e = (tid < NN) ? expf(v - mx) : 0.f;

    float sm = e;
    #pragma unroll
    for (int o = 16; o > 0; o >>= 1) sm += __shfl_xor_sync(0xffffffffu, sm, o);
    if ((tid & 31) == 0) red[tid >> 5] = sm;
    __syncthreads();
    float total = 0.f;
    #pragma unroll
    for (int i = 0; i < 8; i++) total += red[i];

    if (tid < NN) s[tid] = e / total;
}

// ---------------- out = attn @ lv ----------------
__global__ __launch_bounds__(256) void out_gemm(float* __restrict__ out) {
    const int b    = blockIdx.z;
    const int brow = blockIdx.y * 64;
    const int bcol = blockIdx.x * 64;

    __shared__ float As[8][64];
    __shared__ float Bs[8][64];

    const int tid = threadIdx.x;
    const int ty = tid >> 4, tx = tid & 15;

    float acc[4][4];
    #pragma unroll
    for (int i = 0; i < 4; i++)
        #pragma unroll
        for (int j = 0; j < 4; j++) acc[i][j] = 0.f;

    for (int k0 = 0; k0 < NN; k0 += 8) {
        #pragma unroll
        for (int l = tid; l < 512; l += 256) {
            int k = l & 7, n = l >> 3;
            int row = brow + n;
            float v = 0.f;
            if (row < NN)
                v = g_scores[(size_t)(b * NN + row) * NN + k0 + k];
            As[k][n] = v;
        }
        #pragma unroll
        for (int l = tid; l < 512; l += 256) {
            int k = l >> 6, m = l & 63;
            Bs[k][m] = g_lv[(size_t)(b * NN + k0 + k) * HH + bcol + m];
        }
        __syncthreads();

        #pragma unroll
        for (int k = 0; k < 8; k++) {
            float a[4], bb[4];
            #pragma unroll
            for (int i = 0; i < 4; i++) a[i] = As[k][ty * 4 + i];
            #pragma unroll
            for (int j = 0; j < 4; j++) bb[j] = Bs[k][tx * 4 + j];
            #pragma unroll
            for (int i = 0; i < 4; i++)
                #pragma unroll
                for (int j = 0; j < 4; j++)
                    acc[i][j] = fmaf(a[i], bb[j], acc[i][j]);
        }
        __syncthreads();
    }

    #pragma unroll
    for (int i = 0; i < 4; i++) {
        int row = brow + ty * 4 + i;
        if (row >= NN) continue;
        #pragma unroll
        for (int j = 0; j < 4; j++) {
            int col = bcol + tx * 4 + j;
            out[(size_t)(b * NN + row) * HH + col] = acc[i][j];
        }
    }
}

// ---------------- launch ----------------
extern "C" void kernel_launch(void* const* d_in, const int* in_sizes, int n_in,
                              void* d_out, int out_size) {
    const float* input_query = (const float*)d_in[0];
    const float* input_key   = (const float*)d_in[1];
    const float* input_value = (const float*)d_in[2];
    const float* loc_vector  = (const float*)d_in[3];
    const float* Wq   = (const float*)d_in[4];
    const float* bq   = (const float*)d_in[5];
    const float* Wk   = (const float*)d_in[6];
    const float* bk   = (const float*)d_in[7];
    const float* Wv   = (const float*)d_in[8];
    const float* bv   = (const float*)d_in[9];
    const float* Wloc = (const float*)d_in[10];
    const float* bloc = (const float*)d_in[11];
    const float* Wlk  = (const float*)d_in[12];
    const float* blk  = (const float*)d_in[13];
    const float* param = (const float*)d_in[14];
    float* out = (float*)d_out;

    // 0) convert: inputs fp32 -> fp16 hi/lo, weights fp32 -> fp16
    CvtSrc cs;
    cs.p[0] = input_query; cs.p[1] = input_key; cs.p[2] = input_value; cs.p[3] = loc_vector;
    cs.p[4] = Wq; cs.p[5] = Wk; cs.p[6] = Wv; cs.p[7] = Wloc; cs.p[8] = Wlk;
    cvt_split<<<dim3(AELEMS / 1024, 9), 256>>>(cs);

    // 1) five projections on tensor cores (fp16, 2 MMAs per tile)
    proj_mma<<<dim3(HH / 128, MM / 128, 5), 256>>>(bq, bk, bv, bloc, blk);

    // 2) scores (fused q+param / q+lloc adds), scaled
    scores_kernel<<<dim3(4, 4, BB), 256>>>(param);

    // 3) softmax over m
    softmax_kernel<<<MM, 256>>>();

    // 4) attn @ lv -> out
    out_gemm<<<dim3(HH / 64, 4, BB), 256>>>(out);
}